// round 8
// baseline (speedup 1.0000x reference)
#include <cuda_runtime.h>

// Integrate-and-fire: per neuron (b,h,w,c), scan t: v += x; if (v > 2) {spike=1; v=0}
// Two independent 100-step windows (v resets at t==100) -> chunk parallelism.
//
// Topology (best warm-loop behavior, R5): 1024 threads, tile 4w x 32h x 8c,
// scalar pipeline U=5, 2 blocks/SM (~80% occupancy). Moderate per-warp MLP +
// many warps minimizes cross-CTA L1tex-queue spread (straggler tail paid on
// every graph replay).
//   input : warp = fixed h, lane = wl*8+c -> full 128B line
//   output: warp = fixed (w,c), lane = h  -> full 128B line
// Refinements kept from R6/R7: byte smem transpose (pitch 33, conflict-free
// both roles: write = 32 consecutive bytes/warp, read = stride-33 bytes ->
// banks (8*lane + lane/4) mod 32, a permutation), ping-pong register phases
// (no copies), ONE barrier per batch, default-cached input / streaming output.
//
// Input  index: b*6553600 + t*32768 + h*512 + w*8 + c
// Output index: b*6553600 + t*32768 + w*512 + c*64 + h

#define T_CHUNK  100
#define STRIDE_T 32768      // 64*64*8
#define STRIDE_B 6553600    // 200*STRIDE_T
#define VM_THR   2.0f
#define U        5          // batch depth; 100 % (2*U) == 0

__global__ __launch_bounds__(1024, 2)
void iaf_kernel(const float* __restrict__ in, float* __restrict__ out) {
    const int wt    = blockIdx.x >> 1;   // 0..15  (w tile of 4)
    const int hh    = blockIdx.x & 1;    // 0..1   (h half of 32)
    const int b     = blockIdx.y;        // 0..3
    const int chunk = blockIdx.z;        // 0..1
    const int tid   = threadIdx.x;       // 0..1023

    // byte staging: s8[phase][k][hl*33 + wc]; pitch 33 (⊥ 32, ⊥ 128)
    __shared__ unsigned char s8[2][U][32 * 33];

    const size_t base = (size_t)b * STRIDE_B + (size_t)chunk * T_CHUNK * STRIDE_T;

    // input role: hl = h within half (warp id), lane = wl*8+c
    const int hl   = tid >> 5;           // 0..31
    const int lane = tid & 31;           // 0..31
    const float* ip = in + base + (size_t)(hh * 32 + hl) * 512 + wt * 32 + lane;

    // output role: wc_o = wl'*8+c' (warp id), lane = h within half
    const int wc_o = tid >> 5;           // 0..31
    float* op = out + base + (size_t)wt * 2048
              + (wc_o >> 3) * 512 + (wc_o & 7) * 64 + hh * 32 + lane;

    const int swr = hl * 33 + lane;      // byte write slot (lane stride 1)
    const int srd = lane * 33 + wc_o;    // byte read slot  (lane stride 33)

    float reg[2][U];
    #pragma unroll
    for (int k = 0; k < U; k++) reg[0][k] = ip[k * STRIDE_T];   // prime phase 0

    float v = 0.0f;

    #pragma unroll 1
    for (int it = 0; it < T_CHUNK / (2 * U); ++it) {   // 10 batches of U
        #pragma unroll
        for (int ph = 0; ph < 2; ++ph) {               // compile-time phase
            const int tb = it * 2 * U + ph * U;
            // prefetch next batch into the other phase (no register copies)
            if (tb + U < T_CHUNK) {
                #pragma unroll
                for (int k = 0; k < U; k++)
                    reg[ph ^ 1][k] = ip[(tb + U + k) * STRIDE_T];
            }
            // sequential integrate-and-fire; spikes -> smem bytes
            #pragma unroll
            for (int k = 0; k < U; k++) {
                v += reg[ph][k];
                unsigned char sp = 0;
                if (v > VM_THR) { sp = 1; v = 0.0f; }
                s8[ph][k][swr] = sp;
            }
            __syncthreads();   // writes(ph) visible; reads(ph) from the
                               // previous use of this phase completed one
                               // barrier ago -> safe double buffer
            // fully-coalesced 128B streaming stores through the transposed role
            #pragma unroll
            for (int k = 0; k < U; k++)
                __stcs(op + (tb + k) * STRIDE_T, (float)s8[ph][k][srd]);
        }
    }
}

extern "C" void kernel_launch(void* const* d_in, const int* in_sizes, int n_in,
                              void* d_out, int out_size) {
    const float* in = (const float*)d_in[0];
    float* out = (float*)d_out;
    dim3 grid(32, 4, 2);   // (wt*2+hh, b, chunk)
    iaf_kernel<<<grid, 1024>>>(in, out);
}

// round 9
// speedup vs baseline: 1.0164x; 1.0164x over previous
#include <cuda_runtime.h>

// Integrate-and-fire: per neuron (b,h,w,c), scan t: v += x; if (v > 2) {spike=1; v=0}
// Two independent 100-step windows (v resets at t==100) -> chunk parallelism.
//
// Topology (lowest warm-loop spread): 1024 threads, tile 4w x 32h x 8c,
// scalar U=5, 2 blocks/SM (~80% occupancy).
//   input : warp = fixed h, lane = wl*8+c -> full 128B line
//   output: warp = fixed (w,c), lane = h  -> full 128B line
// FLOAT smem transpose (no I2F converts on the store critical path), pitch 33
// (conflict-free both roles), ping-pong phases: ONE barrier per batch and no
// register copies. Cursor-based pointer advance keeps inner-loop ALU minimal.
//
// Input  index: b*6553600 + t*32768 + h*512 + w*8 + c
// Output index: b*6553600 + t*32768 + w*512 + c*64 + h

#define T_CHUNK  100
#define STRIDE_T 32768      // 64*64*8
#define STRIDE_B 6553600    // 200*STRIDE_T
#define VM_THR   2.0f
#define U        5          // batch depth; 100 % (2*U) == 0

__global__ __launch_bounds__(1024, 2)
void iaf_kernel(const float* __restrict__ in, float* __restrict__ out) {
    const int wt    = blockIdx.x >> 1;   // 0..15  (w tile of 4)
    const int hh    = blockIdx.x & 1;    // 0..1   (h half of 32)
    const int b     = blockIdx.y;        // 0..3
    const int chunk = blockIdx.z;        // 0..1
    const int tid   = threadIdx.x;       // 0..1023

    // float staging: s[phase][k][hl*33 + wc]; pitch 33 (33 ⊥ 32) -> both the
    // lane-stride-1 write and lane-stride-33 read are bank-conflict-free.
    __shared__ float s[2][U][32 * 33];

    const size_t base = (size_t)b * STRIDE_B + (size_t)chunk * T_CHUNK * STRIDE_T;

    // input role: hl = h within half (warp id), lane = wl*8+c
    const int hl   = tid >> 5;           // 0..31
    const int lane = tid & 31;           // 0..31
    const float* ip = in + base + (size_t)(hh * 32 + hl) * 512 + wt * 32 + lane;

    // output role: wc_o = wl'*8+c' (warp id), lane = h within half
    const int wc_o = tid >> 5;           // 0..31
    float* op = out + base + (size_t)wt * 2048
              + (wc_o >> 3) * 512 + (wc_o & 7) * 64 + hh * 32 + lane;

    const int swr = hl * 33 + lane;      // write slot (lane stride 1)
    const int srd = lane * 33 + wc_o;    // read slot  (lane stride 33)

    float reg[2][U];
    #pragma unroll
    for (int k = 0; k < U; k++) reg[0][k] = ip[k * STRIDE_T];   // prime phase 0

    const float* ipc = ip + U * STRIDE_T;   // prefetch cursor (next batch)
    float*       opc = op;                  // store cursor (current batch)

    float v = 0.0f;

    #pragma unroll 1
    for (int it = 0; it < T_CHUNK / (2 * U); ++it) {   // 10 outer x 2 phases
        #pragma unroll
        for (int ph = 0; ph < 2; ++ph) {               // compile-time phase
            // prefetch next batch into the other phase (no register copies)
            if (it * 2 + ph < T_CHUNK / U - 1) {
                #pragma unroll
                for (int k = 0; k < U; k++)
                    reg[ph ^ 1][k] = ipc[k * STRIDE_T];
                ipc += U * STRIDE_T;
            }
            // sequential integrate-and-fire; spikes -> smem floats
            #pragma unroll
            for (int k = 0; k < U; k++) {
                v += reg[ph][k];
                float sp = 0.0f;
                if (v > VM_THR) { sp = 1.0f; v = 0.0f; }
                s[ph][k][swr] = sp;
            }
            __syncthreads();   // orders writes(ph) before reads(ph); the next
                               // write to this phase is 2 phases away, always
                               // separated from these reads by >=1 barrier
            // fully-coalesced 128B streaming stores through the transposed role
            #pragma unroll
            for (int k = 0; k < U; k++)
                __stcs(opc + k * STRIDE_T, s[ph][k][srd]);
            opc += U * STRIDE_T;
        }
    }
}

extern "C" void kernel_launch(void* const* d_in, const int* in_sizes, int n_in,
                              void* d_out, int out_size) {
    const float* in = (const float*)d_in[0];
    float* out = (float*)d_out;
    dim3 grid(32, 4, 2);   // (wt*2+hh, b, chunk)
    iaf_kernel<<<grid, 1024>>>(in, out);
}